// round 3
// baseline (speedup 1.0000x reference)
#include <cuda_runtime.h>
#include <math.h>

#define BB   32
#define SS   256
#define ISZ  1024
#define OSZ  1024
#define N4   4096
#define EPSF 1e-5f
#define NBLK 128
#define NTHR 256

typedef unsigned long long ull;

// Scratch (device globals -- no runtime allocation allowed)
__device__ float    g_xproj[BB * SS * N4];    // x @ W_x + b for all timesteps
__device__ float    g_h[BB * OSZ];            // hidden state (global, cross-block)
__device__ float    g_part[2][BB][NBLK];      // LN partial sums [stat][row][block]
__device__ unsigned g_bar;                    // grid barrier counter

// ---------------------------------------------------------------------------
// Packed f32x2 helpers (FFMA2 -- ptxas never emits these from C++)
// ---------------------------------------------------------------------------
__device__ __forceinline__ ull ffma2(ull a, ull b, ull c) {
    ull d;
    asm("fma.rn.f32x2 %0, %1, %2, %3;" : "=l"(d) : "l"(a), "l"(b), "l"(c));
    return d;
}
__device__ __forceinline__ ull pack2(float lo, float hi) {
    ull d;
    asm("mov.b64 %0, {%1, %2};" : "=l"(d) : "f"(lo), "f"(hi));
    return d;
}
__device__ __forceinline__ float2 unpack2(ull v) {
    float2 r;
    asm("mov.b64 {%0, %1}, %2;" : "=f"(r.x), "=f"(r.y) : "l"(v));
    return r;
}

// ---------------------------------------------------------------------------
// Init: h from init_hx (broadcast over batch), reset barrier
// ---------------------------------------------------------------------------
__global__ void init_state(const float* __restrict__ init_hx) {
    int j = blockIdx.x * blockDim.x + threadIdx.x;
    if (j == 0) g_bar = 0;
    if (j < BB * OSZ) g_h[j] = init_hx[j & (OSZ - 1)];
}

// ---------------------------------------------------------------------------
// xproj[row, n] = b[n] + sum_k x[row, k] * W[k, n]      row in [0, B*S)
// f32x2 over k-pairs: x ulonglong2 loads give natural {x[k],x[k+1]} pairs;
// W row-k / row-k+1 float4 loads packed per column (8 packs / 4k on ALU pipe).
// Block (32,8): thread = 4 rows x 4 cols, block tile 32 rows x 128 cols.
// ---------------------------------------------------------------------------
__global__ void xproj_kernel(const float* __restrict__ x,
                             const float* __restrict__ W,
                             const float* __restrict__ bias) {
    const int tx = threadIdx.x, ty = threadIdx.y;
    const int col0 = (blockIdx.x * 32 + tx) * 4;
    const int row0 = blockIdx.y * 32 + ty * 4;

    ull acc2[4][4];
    #pragma unroll
    for (int r = 0; r < 4; r++)
        #pragma unroll
        for (int c = 0; c < 4; c++) acc2[r][c] = 0ull;

    const float* xp = x + (size_t)row0 * ISZ;

    #pragma unroll 2
    for (int k = 0; k < ISZ; k += 4) {
        float4 w0 = *(const float4*)(W + (size_t)(k + 0) * N4 + col0);
        float4 w1 = *(const float4*)(W + (size_t)(k + 1) * N4 + col0);
        float4 w2 = *(const float4*)(W + (size_t)(k + 2) * N4 + col0);
        float4 w3 = *(const float4*)(W + (size_t)(k + 3) * N4 + col0);

        ull wp01[4], wp23[4];
        wp01[0] = pack2(w0.x, w1.x); wp01[1] = pack2(w0.y, w1.y);
        wp01[2] = pack2(w0.z, w1.z); wp01[3] = pack2(w0.w, w1.w);
        wp23[0] = pack2(w2.x, w3.x); wp23[1] = pack2(w2.y, w3.y);
        wp23[2] = pack2(w2.z, w3.z); wp23[3] = pack2(w2.w, w3.w);

        #pragma unroll
        for (int r = 0; r < 4; r++) {
            ulonglong2 xv = __ldg((const ulonglong2*)(xp + (size_t)r * ISZ + k));
            #pragma unroll
            for (int c = 0; c < 4; c++) {
                acc2[r][c] = ffma2(xv.x, wp01[c], acc2[r][c]);
                acc2[r][c] = ffma2(xv.y, wp23[c], acc2[r][c]);
            }
        }
    }

    float4 bv = *(const float4*)(bias + col0);
    #pragma unroll
    for (int r = 0; r < 4; r++) {
        float2 a0 = unpack2(acc2[r][0]);
        float2 a1 = unpack2(acc2[r][1]);
        float2 a2 = unpack2(acc2[r][2]);
        float2 a3 = unpack2(acc2[r][3]);
        float4 o;
        o.x = a0.x + a0.y + bv.x;
        o.y = a1.x + a1.y + bv.y;
        o.z = a2.x + a2.y + bv.z;
        o.w = a3.x + a3.y + bv.w;
        *(float4*)(g_xproj + (size_t)(row0 + r) * N4 + col0) = o;
    }
}

// ---------------------------------------------------------------------------
// Software grid barrier (all NBLK blocks co-resident: 1 block/SM by smem)
// ---------------------------------------------------------------------------
__device__ __forceinline__ void gsync(unsigned target) {
    __syncthreads();
    if (threadIdx.x == 0) {
        __threadfence();
        atomicAdd(&g_bar, 1u);
        while (*(volatile unsigned*)&g_bar < target) { }
        __threadfence();
    }
    __syncthreads();
}

// ---------------------------------------------------------------------------
// Persistent LSTM recurrence. Block `blk` owns output indices
// i = blk*8 .. blk*8+7 and their 4 gate columns {g*1024 + i}.
// W_h slice cached in SMEM, k-pair interleaved: float index
//   (k/2)*64 + col*2 + (k&1)  -> thread tx reads LDS.64 {w[k],w[k+1]} pairs.
// Thread (tx, ty): tx -> one of 32 cols (g = tx>>3, q = tx&7),
//                  ty -> batch rows ty*4 .. ty*4+3.
// ---------------------------------------------------------------------------
__global__ void __launch_bounds__(NTHR, 1)
lstm_persist(const float* __restrict__ W,
             const float* __restrict__ gamma,
             const float* __restrict__ beta,
             const float* __restrict__ init_cx,
             float* __restrict__ out) {
    extern __shared__ float Ws[];            // [512][32][2] k-pair interleaved
    __shared__ float c_sm[BB * 8];           // cell state slice (b, q)

    const int tid = threadIdx.x;
    const int tx  = tid & 31, ty = tid >> 5;
    const int blk = blockIdx.x;
    const int g   = tx >> 3, q = tx & 7;
    const int gcol = g * OSZ + blk * 8 + q;  // column in [0, 4096)
    const int b0  = ty * 4;

    // Preload W_h slice, k-pair interleaved
    for (int idx = tid; idx < ISZ * 32; idx += NTHR) {
        int k = idx >> 5, c = idx & 31;
        int col = (c >> 3) * OSZ + blk * 8 + (c & 7);
        Ws[(k >> 1) * 64 + c * 2 + (k & 1)] = W[(size_t)(ISZ + k) * N4 + col];
    }
    if (tid < BB * 8)
        c_sm[tid] = init_cx[blk * 8 + (tid & 7)];

    const float gam = gamma[gcol];
    const float bet = beta[gcol];
    __syncthreads();

    const ull* __restrict__ Wp = (const ull*)Ws;
    unsigned nsync = 0;

    // Prefetch xproj for t=0
    float px[4];
    #pragma unroll
    for (int r = 0; r < 4; r++)
        px[r] = __ldcg(&g_xproj[((size_t)(b0 + r) * SS + 0) * N4 + gcol]);

    for (int t = 0; t < SS; t++) {
        float cur[4];
        #pragma unroll
        for (int r = 0; r < 4; r++) cur[r] = px[r];
        if (t + 1 < SS) {
            #pragma unroll
            for (int r = 0; r < 4; r++)
                px[r] = __ldcg(&g_xproj[((size_t)(b0 + r) * SS + t + 1) * N4 + gcol]);
        }

        // ---- recurrent GEMM in f32x2: two accumulator chains per row ----
        ull aA[4], aB[4];
        #pragma unroll
        for (int r = 0; r < 4; r++) { aA[r] = 0ull; aB[r] = 0ull; }

        #pragma unroll 4
        for (int k = 0; k < ISZ; k += 8) {
            ulonglong2 hA[4], hB[4];   // rows r: {h[k..k+3]}, {h[k+4..k+7]}
            #pragma unroll
            for (int r = 0; r < 4; r++) {
                hA[r] = __ldcg((const ulonglong2*)(g_h + (size_t)(b0 + r) * OSZ + k));
                hB[r] = __ldcg((const ulonglong2*)(g_h + (size_t)(b0 + r) * OSZ + k + 4));
            }
            const int p = (k >> 1) * 32 + tx;
            ull w0 = Wp[p];            // {W[k],   W[k+1]}
            ull w1 = Wp[p + 32];       // {W[k+2], W[k+3]}
            ull w2 = Wp[p + 64];       // {W[k+4], W[k+5]}
            ull w3 = Wp[p + 96];       // {W[k+6], W[k+7]}
            #pragma unroll
            for (int r = 0; r < 4; r++) {
                aA[r] = ffma2(hA[r].x, w0, aA[r]);
                aB[r] = ffma2(hA[r].y, w1, aB[r]);
                aA[r] = ffma2(hB[r].x, w2, aA[r]);
                aB[r] = ffma2(hB[r].y, w3, aB[r]);
            }
        }

        float acc[4];
        #pragma unroll
        for (int r = 0; r < 4; r++) {
            float2 a = unpack2(aA[r]);
            float2 b = unpack2(aB[r]);
            acc[r] = ((a.x + a.y) + (b.x + b.y)) + cur[r];
        }

        // ---- LN partial sums over this block's 32 columns, per row ----
        float s[4], ss[4];
        #pragma unroll
        for (int r = 0; r < 4; r++) { s[r] = acc[r]; ss[r] = acc[r] * acc[r]; }
        #pragma unroll
        for (int o = 16; o > 0; o >>= 1) {
            #pragma unroll
            for (int r = 0; r < 4; r++) {
                s[r]  += __shfl_xor_sync(0xffffffffu, s[r],  o);
                ss[r] += __shfl_xor_sync(0xffffffffu, ss[r], o);
            }
        }
        if (tx == 0) {
            #pragma unroll
            for (int r = 0; r < 4; r++) {
                __stcg(&g_part[0][b0 + r][blk], s[r]);
                __stcg(&g_part[1][b0 + r][blk], ss[r]);
            }
        }

        gsync(++nsync * NBLK);

        // ---- aggregate stats (deterministic): warp ty handles rows b0..b0+3 ----
        float mean[4], rstd[4];
        #pragma unroll
        for (int r = 0; r < 4; r++) {
            int row = b0 + r;
            float4 sv = __ldcg((const float4*)&g_part[0][row][tx * 4]);
            float4 qv = __ldcg((const float4*)&g_part[1][row][tx * 4]);
            float sl = (sv.x + sv.y) + (sv.z + sv.w);
            float ql = (qv.x + qv.y) + (qv.z + qv.w);
            #pragma unroll
            for (int o = 16; o > 0; o >>= 1) {
                sl += __shfl_xor_sync(0xffffffffu, sl, o);
                ql += __shfl_xor_sync(0xffffffffu, ql, o);
            }
            float m = sl * (1.0f / N4);
            mean[r] = m;
            rstd[r] = rsqrtf(ql * (1.0f / N4) - m * m + EPSF);
        }

        // ---- LN + gates. The 4 gates of index i sit in lanes q, q+8, q+16, q+24 ----
        #pragma unroll
        for (int r = 0; r < 4; r++) {
            float v = (acc[r] - mean[r]) * rstd[r] * gam + bet;
            float a0 = __shfl_sync(0xffffffffu, v, q);        // ig
            float a1 = __shfl_sync(0xffffffffu, v, q + 8);    // fg
            float a2 = __shfl_sync(0xffffffffu, v, q + 16);   // hidden
            float a3 = __shfl_sync(0xffffffffu, v, q + 24);   // og
            if (g == 0) {
                int b = b0 + r;
                int i = blk * 8 + q;
                float si = 1.0f / (1.0f + expf(-a0));
                float sf = 1.0f / (1.0f + expf(-a1));
                float so = 1.0f / (1.0f + expf(-a3));
                float co = c_sm[b * 8 + q];
                float cn = sf * co + si * tanhf(a2);
                float h  = so * cn;
                c_sm[b * 8 + q] = cn;
                __stcg(&g_h[(size_t)b * OSZ + i], h);
                out[((size_t)b * SS + t) * OSZ + i] = h;
            }
        }

        gsync(++nsync * NBLK);
    }
}

// ---------------------------------------------------------------------------
// Inputs (metadata order): x, W, b, gamma, beta, init_hx, init_cx
// ---------------------------------------------------------------------------
extern "C" void kernel_launch(void* const* d_in, const int* in_sizes, int n_in,
                              void* d_out, int out_size) {
    const float* x       = (const float*)d_in[0];
    const float* W       = (const float*)d_in[1];
    const float* bias    = (const float*)d_in[2];
    const float* gamma   = (const float*)d_in[3];
    const float* beta    = (const float*)d_in[4];
    const float* init_hx = (const float*)d_in[5];
    const float* init_cx = (const float*)d_in[6];
    float* out = (float*)d_out;

    init_state<<<(BB * OSZ + 255) / 256, 256>>>(init_hx);

    dim3 blk(32, 8);
    xproj_kernel<<<dim3(32, 256), blk>>>(x, W, bias);

    cudaFuncSetAttribute(lstm_persist,
                         cudaFuncAttributeMaxDynamicSharedMemorySize, 131072);
    lstm_persist<<<NBLK, NTHR, 131072>>>(W, gamma, beta, init_cx, out);
}

// round 4
// speedup vs baseline: 2.3697x; 2.3697x over previous
#include <cuda_runtime.h>
#include <math.h>

#define BB     32
#define SS     256
#define ISZ    1024
#define OSZ    1024
#define N4     4096
#define EPSF   1e-5f
#define NBLK   128
#define NTHR   256
#define CHUNK  256                 // k-extent per staged chunk
#define NCH    4                   // 1024 / 256

// Scratch (device globals -- no runtime allocation allowed)
__device__ float    g_xproj[BB * SS * N4];    // x @ W_x + b for all timesteps
__device__ float    g_h[BB * OSZ];            // hidden state (global, cross-block)
__device__ float    g_part[2][BB][NBLK];      // LN partial sums [stat][row][block]
__device__ unsigned g_bar;                    // grid barrier counter

// ---------------------------------------------------------------------------
// Init: h from init_hx (broadcast over batch), reset barrier
// ---------------------------------------------------------------------------
__global__ void init_state(const float* __restrict__ init_hx) {
    int j = blockIdx.x * blockDim.x + threadIdx.x;
    if (j == 0) g_bar = 0;
    if (j < BB * OSZ) g_h[j] = init_hx[j & (OSZ - 1)];
}

// ---------------------------------------------------------------------------
// xproj[row, n] = b[n] + sum_k x[row, k] * W[k, n]      (round-2 proven form)
// Block (32,8): thread = 4 rows x 4 cols, block tile 32 rows x 128 cols.
// ---------------------------------------------------------------------------
__global__ void xproj_kernel(const float* __restrict__ x,
                             const float* __restrict__ W,
                             const float* __restrict__ bias) {
    const int tx = threadIdx.x, ty = threadIdx.y;
    const int col0 = (blockIdx.x * 32 + tx) * 4;
    const int row0 = blockIdx.y * 32 + ty * 4;

    float acc[4][4] = {};
    const float* xp = x + (size_t)row0 * ISZ;

    #pragma unroll 4
    for (int k = 0; k < ISZ; k++) {
        float4 w = *(const float4*)(W + (size_t)k * N4 + col0);
        #pragma unroll
        for (int r = 0; r < 4; r++) {
            float xv = __ldg(xp + (size_t)r * ISZ + k);
            acc[r][0] += xv * w.x;
            acc[r][1] += xv * w.y;
            acc[r][2] += xv * w.z;
            acc[r][3] += xv * w.w;
        }
    }

    float4 bv = *(const float4*)(bias + col0);
    #pragma unroll
    for (int r = 0; r < 4; r++) {
        float4 o;
        o.x = acc[r][0] + bv.x;
        o.y = acc[r][1] + bv.y;
        o.z = acc[r][2] + bv.z;
        o.w = acc[r][3] + bv.w;
        *(float4*)(g_xproj + (size_t)(row0 + r) * N4 + col0) = o;
    }
}

// ---------------------------------------------------------------------------
// Software grid barrier (all NBLK blocks co-resident: 1 block/SM by smem)
// ---------------------------------------------------------------------------
__device__ __forceinline__ void gsync(unsigned target) {
    __syncthreads();
    if (threadIdx.x == 0) {
        __threadfence();
        atomicAdd(&g_bar, 1u);
        while (*(volatile unsigned*)&g_bar < target) { }
        __threadfence();
    }
    __syncthreads();
}

// ---------------------------------------------------------------------------
// Persistent LSTM recurrence.
// Block `blk` owns output cols {g*1024 + blk*8 + q : g in 0..3, q in 0..7}.
// SMEM: W slice as float4 [k/4][32 cols]  (131072 B)
//       h staged in 2 x 32KB chunk buffers (65536 B), broadcast-read.
// Thread (tx, ty): tx -> col (g=tx>>3, q=tx&7), ty -> rows ty*4..ty*4+3.
// ---------------------------------------------------------------------------
__global__ void __launch_bounds__(NTHR, 1)
lstm_persist(const float* __restrict__ W,
             const float* __restrict__ gamma,
             const float* __restrict__ beta,
             const float* __restrict__ init_cx,
             float* __restrict__ out) {
    extern __shared__ float smem[];
    float4* __restrict__ Wsf4 = (float4*)smem;              // [8192]
    float4* __restrict__ Hbuf = (float4*)(smem + 32768);    // [2][2048]
    __shared__ float c_sm[BB * 8];

    const int tid = threadIdx.x;
    const int tx  = tid & 31, ty = tid >> 5;
    const int blk = blockIdx.x;
    const int g   = tx >> 3, q = tx & 7;
    const int gcol = g * OSZ + blk * 8 + q;
    const int b0  = ty * 4;

    // Preload W_h slice into float4 layout: smem[(k>>2)*128 + c*4 + (k&3)]
    for (int idx = tid; idx < ISZ * 32; idx += NTHR) {
        int k = idx >> 5, c = idx & 31;
        int col = (c >> 3) * OSZ + blk * 8 + (c & 7);
        smem[(k >> 2) * 128 + c * 4 + (k & 3)] = W[(size_t)(ISZ + k) * N4 + col];
    }
    if (tid < BB * 8)
        c_sm[tid] = init_cx[blk * 8 + (tid & 7)];

    const float gam = gamma[gcol];
    const float bet = beta[gcol];

    // Cooperative-load source indices for this thread (8 float4 per chunk)
    // linear i = u*256 + tid over 2048 float4: row r = i>>6, j = i&63
    int ld_r[8], ld_j[8];
    #pragma unroll
    for (int u = 0; u < 8; u++) {
        int i = u * NTHR + tid;
        ld_r[u] = i >> 6;
        ld_j[u] = i & 63;
    }
    __syncthreads();

    unsigned nsync = 0;

    // Prefetch xproj for t=0
    float px[4];
    #pragma unroll
    for (int r = 0; r < 4; r++)
        px[r] = __ldcg(&g_xproj[((size_t)(b0 + r) * SS + 0) * N4 + gcol]);

    for (int t = 0; t < SS; t++) {
        float cur[4];
        #pragma unroll
        for (int r = 0; r < 4; r++) cur[r] = px[r];
        if (t + 1 < SS) {
            #pragma unroll
            for (int r = 0; r < 4; r++)
                px[r] = __ldcg(&g_xproj[((size_t)(b0 + r) * SS + t + 1) * N4 + gcol]);
        }

        // ---- stage chunk 0 of h ----
        {
            float4 ld[8];
            #pragma unroll
            for (int u = 0; u < 8; u++)
                ld[u] = __ldcg((const float4*)(g_h + (size_t)ld_r[u] * OSZ + ld_j[u] * 4));
            #pragma unroll
            for (int u = 0; u < 8; u++)
                Hbuf[u * NTHR + tid] = ld[u];
        }
        __syncthreads();

        // ---- recurrent GEMM over 4 chunks, double-buffered ----
        float acc[4] = {0.f, 0.f, 0.f, 0.f};

        #pragma unroll
        for (int c = 0; c < NCH; c++) {
            float4 ldn[8];
            if (c < NCH - 1) {
                const int k0n = (c + 1) * CHUNK;
                #pragma unroll
                for (int u = 0; u < 8; u++)
                    ldn[u] = __ldcg((const float4*)(g_h + (size_t)ld_r[u] * OSZ + k0n + ld_j[u] * 4));
            }

            const float4* __restrict__ hb = Hbuf + (c & 1) * 2048;
            const float4* __restrict__ wp = Wsf4 + (size_t)(c * 64) * 32 + tx;

            #pragma unroll 4
            for (int kk = 0; kk < 64; kk++) {
                float4 w4 = wp[kk * 32];
                float4 h0 = hb[(b0 + 0) * 64 + kk];
                float4 h1 = hb[(b0 + 1) * 64 + kk];
                float4 h2 = hb[(b0 + 2) * 64 + kk];
                float4 h3 = hb[(b0 + 3) * 64 + kk];
                acc[0] += h0.x * w4.x + h0.y * w4.y + h0.z * w4.z + h0.w * w4.w;
                acc[1] += h1.x * w4.x + h1.y * w4.y + h1.z * w4.z + h1.w * w4.w;
                acc[2] += h2.x * w4.x + h2.y * w4.y + h2.z * w4.z + h2.w * w4.w;
                acc[3] += h3.x * w4.x + h3.y * w4.y + h3.z * w4.z + h3.w * w4.w;
            }

            if (c < NCH - 1) {
                float4* __restrict__ hn = Hbuf + ((c + 1) & 1) * 2048;
                #pragma unroll
                for (int u = 0; u < 8; u++)
                    hn[u * NTHR + tid] = ldn[u];
                __syncthreads();
            }
        }

        #pragma unroll
        for (int r = 0; r < 4; r++) acc[r] += cur[r];

        // ---- LN partial sums over this block's 32 columns, per row ----
        float s[4], ss[4];
        #pragma unroll
        for (int r = 0; r < 4; r++) { s[r] = acc[r]; ss[r] = acc[r] * acc[r]; }
        #pragma unroll
        for (int o = 16; o > 0; o >>= 1) {
            #pragma unroll
            for (int r = 0; r < 4; r++) {
                s[r]  += __shfl_xor_sync(0xffffffffu, s[r],  o);
                ss[r] += __shfl_xor_sync(0xffffffffu, ss[r], o);
            }
        }
        if (tx == 0) {
            #pragma unroll
            for (int r = 0; r < 4; r++) {
                __stcg(&g_part[0][b0 + r][blk], s[r]);
                __stcg(&g_part[1][b0 + r][blk], ss[r]);
            }
        }

        gsync(++nsync * NBLK);

        // ---- aggregate stats (deterministic): warp ty handles rows b0..b0+3 ----
        float mean[4], rstd[4];
        #pragma unroll
        for (int r = 0; r < 4; r++) {
            int row = b0 + r;
            float4 sv = __ldcg((const float4*)&g_part[0][row][tx * 4]);
            float4 qv = __ldcg((const float4*)&g_part[1][row][tx * 4]);
            float sl = (sv.x + sv.y) + (sv.z + sv.w);
            float ql = (qv.x + qv.y) + (qv.z + qv.w);
            #pragma unroll
            for (int o = 16; o > 0; o >>= 1) {
                sl += __shfl_xor_sync(0xffffffffu, sl, o);
                ql += __shfl_xor_sync(0xffffffffu, ql, o);
            }
            float m = sl * (1.0f / N4);
            mean[r] = m;
            rstd[r] = rsqrtf(ql * (1.0f / N4) - m * m + EPSF);
        }

        // ---- LN + gates. Gates of index i sit in lanes q, q+8, q+16, q+24 ----
        #pragma unroll
        for (int r = 0; r < 4; r++) {
            float v = (acc[r] - mean[r]) * rstd[r] * gam + bet;
            float a0 = __shfl_sync(0xffffffffu, v, q);        // ig
            float a1 = __shfl_sync(0xffffffffu, v, q + 8);    // fg
            float a2 = __shfl_sync(0xffffffffu, v, q + 16);   // hidden
            float a3 = __shfl_sync(0xffffffffu, v, q + 24);   // og
            if (g == 0) {
                int b = b0 + r;
                int i = blk * 8 + q;
                float si = 1.0f / (1.0f + expf(-a0));
                float sf = 1.0f / (1.0f + expf(-a1));
                float so = 1.0f / (1.0f + expf(-a3));
                float co = c_sm[b * 8 + q];
                float cn = sf * co + si * tanhf(a2);
                float h  = so * cn;
                c_sm[b * 8 + q] = cn;
                __stcg(&g_h[(size_t)b * OSZ + i], h);
                out[((size_t)b * SS + t) * OSZ + i] = h;
            }
        }

        gsync(++nsync * NBLK);
    }
}

// ---------------------------------------------------------------------------
// Inputs (metadata order): x, W, b, gamma, beta, init_hx, init_cx
// ---------------------------------------------------------------------------
extern "C" void kernel_launch(void* const* d_in, const int* in_sizes, int n_in,
                              void* d_out, int out_size) {
    const float* x       = (const float*)d_in[0];
    const float* W       = (const float*)d_in[1];
    const float* bias    = (const float*)d_in[2];
    const float* gamma   = (const float*)d_in[3];
    const float* beta    = (const float*)d_in[4];
    const float* init_hx = (const float*)d_in[5];
    const float* init_cx = (const float*)d_in[6];
    float* out = (float*)d_out;

    init_state<<<(BB * OSZ + 255) / 256, 256>>>(init_hx);

    dim3 blk(32, 8);
    xproj_kernel<<<dim3(32, 256), blk>>>(x, W, bias);

    cudaFuncSetAttribute(lstm_persist,
                         cudaFuncAttributeMaxDynamicSharedMemorySize, 196608);
    lstm_persist<<<NBLK, NTHR, 196608>>>(W, gamma, beta, init_cx, out);
}

// round 5
// speedup vs baseline: 2.6839x; 1.1326x over previous
#include <cuda_runtime.h>
#include <math.h>

#define BB     32
#define SS     256
#define ISZ    1024
#define OSZ    1024
#define N4     4096
#define EPSF   1e-5f
#define NBLK   128
#define NTHR   256
#define CHUNK  256                 // k-extent per staged chunk
#define NCH    4                   // 1024 / 256

typedef unsigned long long ull;

// Scratch (device globals -- no runtime allocation allowed)
__device__ float    g_xproj[BB * SS * N4];    // x @ W_x + b for all timesteps
__device__ float    g_h[BB * OSZ];            // hidden state (global, cross-block)
__device__ float    g_part[2][BB][NBLK];      // LN partial sums [stat][row][block]
__device__ unsigned g_bar;                    // grid barrier counter

// ---------------------------------------------------------------------------
// Packed f32x2 helpers (FFMA2 -- exact fp32 x2 per instruction)
// ---------------------------------------------------------------------------
__device__ __forceinline__ ull ffma2(ull a, ull b, ull c) {
    ull d;
    asm("fma.rn.f32x2 %0, %1, %2, %3;" : "=l"(d) : "l"(a), "l"(b), "l"(c));
    return d;
}
__device__ __forceinline__ float2 unpack2(ull v) {
    float2 r;
    asm("mov.b64 {%0, %1}, %2;" : "=f"(r.x), "=f"(r.y) : "l"(v));
    return r;
}

// ---------------------------------------------------------------------------
// Init: h from init_hx (broadcast over batch), reset barrier
// ---------------------------------------------------------------------------
__global__ void init_state(const float* __restrict__ init_hx) {
    int j = blockIdx.x * blockDim.x + threadIdx.x;
    if (j == 0) g_bar = 0;
    if (j < BB * OSZ) g_h[j] = init_hx[j & (OSZ - 1)];
}

// ---------------------------------------------------------------------------
// xproj[row, n] = b[n] + sum_k x[row, k] * W[k, n]      (proven R2/R4 form)
// ---------------------------------------------------------------------------
__global__ void xproj_kernel(const float* __restrict__ x,
                             const float* __restrict__ W,
                             const float* __restrict__ bias) {
    const int tx = threadIdx.x, ty = threadIdx.y;
    const int col0 = (blockIdx.x * 32 + tx) * 4;
    const int row0 = blockIdx.y * 32 + ty * 4;

    float acc[4][4] = {};
    const float* xp = x + (size_t)row0 * ISZ;

    #pragma unroll 4
    for (int k = 0; k < ISZ; k++) {
        float4 w = *(const float4*)(W + (size_t)k * N4 + col0);
        #pragma unroll
        for (int r = 0; r < 4; r++) {
            float xv = __ldg(xp + (size_t)r * ISZ + k);
            acc[r][0] += xv * w.x;
            acc[r][1] += xv * w.y;
            acc[r][2] += xv * w.z;
            acc[r][3] += xv * w.w;
        }
    }

    float4 bv = *(const float4*)(bias + col0);
    #pragma unroll
    for (int r = 0; r < 4; r++) {
        float4 o;
        o.x = acc[r][0] + bv.x;
        o.y = acc[r][1] + bv.y;
        o.z = acc[r][2] + bv.z;
        o.w = acc[r][3] + bv.w;
        *(float4*)(g_xproj + (size_t)(row0 + r) * N4 + col0) = o;
    }
}

// ---------------------------------------------------------------------------
// Software grid barrier (all NBLK blocks co-resident: 1 block/SM by smem)
// ---------------------------------------------------------------------------
__device__ __forceinline__ void gsync(unsigned target) {
    __syncthreads();
    if (threadIdx.x == 0) {
        __threadfence();
        atomicAdd(&g_bar, 1u);
        while (*(volatile unsigned*)&g_bar < target) { }
        __threadfence();
    }
    __syncthreads();
}

// ---------------------------------------------------------------------------
// Persistent LSTM recurrence.
// Block `blk` owns output cols {g*1024 + blk*8 + q}.
// Warp mapping: tx -> col, ty -> k-subrange [ty*32, ty*32+32) of each chunk,
// accumulating partials for ALL 32 batch rows (32 x f32x2 accumulators).
// Per step: partials reduced across the 8 warps via a SMEM buffer that
// overlays the (dead) chunk-0 h staging buffer.
// SMEM: W slice float4 [k/4][32 cols] (128KB) + h double buffer (64KB).
// ---------------------------------------------------------------------------
__global__ void __launch_bounds__(NTHR, 1)
lstm_persist(const float* __restrict__ W,
             const float* __restrict__ gamma,
             const float* __restrict__ beta,
             const float* __restrict__ init_cx,
             float* __restrict__ out) {
    extern __shared__ float smem[];
    float4* __restrict__ Wsf4 = (float4*)smem;               // [8192] float4
    float*  __restrict__ Hreg = smem + 32768;                // 64KB region
    float4* __restrict__ Hbuf = (float4*)Hreg;               // [2][2048] float4
    float*  __restrict__ Pred = Hreg;                        // overlay: [32][8][32]
    __shared__ float c_sm[BB * 8];

    const int tid = threadIdx.x;
    const int tx  = tid & 31, ty = tid >> 5;
    const int blk = blockIdx.x;
    const int g   = tx >> 3, q = tx & 7;
    const int gcol = g * OSZ + blk * 8 + q;
    const int b0  = ty * 4;

    // Preload W_h slice into float4 layout: smem[(k>>2)*128 + c*4 + (k&3)]
    for (int idx = tid; idx < ISZ * 32; idx += NTHR) {
        int k = idx >> 5, c = idx & 31;
        int col = (c >> 3) * OSZ + blk * 8 + (c & 7);
        smem[(k >> 2) * 128 + c * 4 + (k & 3)] = W[(size_t)(ISZ + k) * N4 + col];
    }
    if (tid < BB * 8)
        c_sm[tid] = init_cx[blk * 8 + (tid & 7)];

    const float gam = gamma[gcol];
    const float bet = beta[gcol];

    // Cooperative-load source indices (8 float4 per chunk per thread)
    int ld_r[8], ld_j[8];
    #pragma unroll
    for (int u = 0; u < 8; u++) {
        int i = u * NTHR + tid;
        ld_r[u] = i >> 6;
        ld_j[u] = i & 63;
    }
    __syncthreads();

    unsigned nsync = 0;

    // Prefetch xproj for t=0
    float px[4];
    #pragma unroll
    for (int r = 0; r < 4; r++)
        px[r] = __ldcg(&g_xproj[((size_t)(b0 + r) * SS + 0) * N4 + gcol]);

    for (int t = 0; t < SS; t++) {
        float cur[4];
        #pragma unroll
        for (int r = 0; r < 4; r++) cur[r] = px[r];
        if (t + 1 < SS) {
            #pragma unroll
            for (int r = 0; r < 4; r++)
                px[r] = __ldcg(&g_xproj[((size_t)(b0 + r) * SS + t + 1) * N4 + gcol]);
        }

        // ---- stage chunk 0 of h ----
        {
            float4 ld[8];
            #pragma unroll
            for (int u = 0; u < 8; u++)
                ld[u] = __ldcg((const float4*)(g_h + (size_t)ld_r[u] * OSZ + ld_j[u] * 4));
            #pragma unroll
            for (int u = 0; u < 8; u++)
                Hbuf[u * NTHR + tid] = ld[u];
        }
        __syncthreads();

        // ---- recurrent GEMM: warp ty covers k in [c*256+ty*32, +32) for
        //      all 32 rows; f32x2 accumulators, one per row ----
        ull acc2[32];
        #pragma unroll
        for (int r = 0; r < 32; r++) acc2[r] = 0ull;

        #pragma unroll 1
        for (int c = 0; c < NCH; c++) {
            float4 ldn[8];
            if (c < NCH - 1) {
                const int k0n = (c + 1) * CHUNK;
                #pragma unroll
                for (int u = 0; u < 8; u++)
                    ldn[u] = __ldcg((const float4*)(g_h + (size_t)ld_r[u] * OSZ + k0n + ld_j[u] * 4));
            }

            const float4* __restrict__ hb = Hbuf + (c & 1) * 2048;
            const ulonglong2* __restrict__ wp =
                (const ulonglong2*)Wsf4 + (size_t)(c * 64 + ty * 8) * 32 + tx;

            #pragma unroll 4
            for (int jj = 0; jj < 8; jj++) {
                ulonglong2 wv = wp[jj * 32];            // {w[k],w[k+1]},{w[k+2],w[k+3]}
                const ulonglong2* __restrict__ hj =
                    (const ulonglong2*)(hb + (ty * 8 + jj));
                #pragma unroll
                for (int r = 0; r < 32; r++) {
                    ulonglong2 hv = hj[r * 64];         // broadcast: h[r][k..k+3]
                    acc2[r] = ffma2(hv.x, wv.x, acc2[r]);
                    acc2[r] = ffma2(hv.y, wv.y, acc2[r]);
                }
            }

            if (c < NCH - 1) {
                float4* __restrict__ hn = Hbuf + ((c + 1) & 1) * 2048;
                #pragma unroll
                for (int u = 0; u < 8; u++)
                    hn[u * NTHR + tid] = ldn[u];
                __syncthreads();
            }
        }

        // ---- cross-warp k-reduction via SMEM overlay (buf0 region is dead:
        //      final chunk reads buf1 only) ----
        #pragma unroll
        for (int r = 0; r < 32; r++) {
            float2 a = unpack2(acc2[r]);
            Pred[(r * 8 + ty) * 32 + tx] = a.x + a.y;
        }
        __syncthreads();

        float acc[4];
        #pragma unroll
        for (int r = 0; r < 4; r++) {
            const int row = b0 + r;
            float sum = 0.f;
            #pragma unroll
            for (int w = 0; w < 8; w++)
                sum += Pred[(row * 8 + w) * 32 + tx];
            acc[r] = sum + cur[r];
        }

        // ---- LN partial sums over this block's 32 columns, per row ----
        float s[4], ss[4];
        #pragma unroll
        for (int r = 0; r < 4; r++) { s[r] = acc[r]; ss[r] = acc[r] * acc[r]; }
        #pragma unroll
        for (int o = 16; o > 0; o >>= 1) {
            #pragma unroll
            for (int r = 0; r < 4; r++) {
                s[r]  += __shfl_xor_sync(0xffffffffu, s[r],  o);
                ss[r] += __shfl_xor_sync(0xffffffffu, ss[r], o);
            }
        }
        if (tx == 0) {
            #pragma unroll
            for (int r = 0; r < 4; r++) {
                __stcg(&g_part[0][b0 + r][blk], s[r]);
                __stcg(&g_part[1][b0 + r][blk], ss[r]);
            }
        }

        gsync(++nsync * NBLK);

        // ---- aggregate stats (deterministic): warp ty handles rows b0..b0+3 ----
        float mean[4], rstd[4];
        #pragma unroll
        for (int r = 0; r < 4; r++) {
            int row = b0 + r;
            float4 sv = __ldcg((const float4*)&g_part[0][row][tx * 4]);
            float4 qv = __ldcg((const float4*)&g_part[1][row][tx * 4]);
            float sl = (sv.x + sv.y) + (sv.z + sv.w);
            float ql = (qv.x + qv.y) + (qv.z + qv.w);
            #pragma unroll
            for (int o = 16; o > 0; o >>= 1) {
                sl += __shfl_xor_sync(0xffffffffu, sl, o);
                ql += __shfl_xor_sync(0xffffffffu, ql, o);
            }
            float m = sl * (1.0f / N4);
            mean[r] = m;
            rstd[r] = rsqrtf(ql * (1.0f / N4) - m * m + EPSF);
        }

        // ---- LN + gates. Gates of index i sit in lanes q, q+8, q+16, q+24 ----
        #pragma unroll
        for (int r = 0; r < 4; r++) {
            float v = (acc[r] - mean[r]) * rstd[r] * gam + bet;
            float a0 = __shfl_sync(0xffffffffu, v, q);        // ig
            float a1 = __shfl_sync(0xffffffffu, v, q + 8);    // fg
            float a2 = __shfl_sync(0xffffffffu, v, q + 16);   // hidden
            float a3 = __shfl_sync(0xffffffffu, v, q + 24);   // og
            if (g == 0) {
                int b = b0 + r;
                int i = blk * 8 + q;
                float si = 1.0f / (1.0f + expf(-a0));
                float sf = 1.0f / (1.0f + expf(-a1));
                float so = 1.0f / (1.0f + expf(-a3));
                float co = c_sm[b * 8 + q];
                float cn = sf * co + si * tanhf(a2);
                float h  = so * cn;
                c_sm[b * 8 + q] = cn;
                __stcg(&g_h[(size_t)b * OSZ + i], h);
                out[((size_t)b * SS + t) * OSZ + i] = h;
            }
        }

        gsync(++nsync * NBLK);
    }
}

// ---------------------------------------------------------------------------
// Inputs (metadata order): x, W, b, gamma, beta, init_hx, init_cx
// ---------------------------------------------------------------------------
extern "C" void kernel_launch(void* const* d_in, const int* in_sizes, int n_in,
                              void* d_out, int out_size) {
    const float* x       = (const float*)d_in[0];
    const float* W       = (const float*)d_in[1];
    const float* bias    = (const float*)d_in[2];
    const float* gamma   = (const float*)d_in[3];
    const float* beta    = (const float*)d_in[4];
    const float* init_hx = (const float*)d_in[5];
    const float* init_cx = (const float*)d_in[6];
    float* out = (float*)d_out;

    init_state<<<(BB * OSZ + 255) / 256, 256>>>(init_hx);

    dim3 blk(32, 8);
    xproj_kernel<<<dim3(32, 256), blk>>>(x, W, bias);

    cudaFuncSetAttribute(lstm_persist,
                         cudaFuncAttributeMaxDynamicSharedMemorySize, 196608);
    lstm_persist<<<NBLK, NTHR, 196608>>>(W, gamma, beta, init_cx, out);
}

// round 6
// speedup vs baseline: 2.8034x; 1.0445x over previous
#include <cuda_runtime.h>
#include <math.h>

#define BB     32
#define SS     256
#define ISZ    1024
#define OSZ    1024
#define N4     4096
#define EPSF   1e-5f
#define NBLK   128
#define NTHR   256
#define CHUNK  256                 // k-extent per staged chunk
#define NCH    4                   // 1024 / 256

typedef unsigned long long ull;

// Scratch (device globals -- no runtime allocation allowed)
__device__ float    g_xproj[BB * SS * N4];    // x @ W_x + b for all timesteps
__device__ float    g_h[BB * OSZ];            // hidden state (global, cross-block)
__device__ float    g_part[2][BB][NBLK];      // LN partial sums [stat][row][block]
__device__ unsigned g_bar;                    // grid barrier counter

// ---------------------------------------------------------------------------
// Packed f32x2 helpers (FFMA2 -- exact fp32 x2 per instruction)
// ---------------------------------------------------------------------------
__device__ __forceinline__ ull ffma2(ull a, ull b, ull c) {
    ull d;
    asm("fma.rn.f32x2 %0, %1, %2, %3;" : "=l"(d) : "l"(a), "l"(b), "l"(c));
    return d;
}
__device__ __forceinline__ ull splat2(float f) {
    ull d;
    asm("mov.b64 %0, {%1, %1};" : "=l"(d) : "f"(f));
    return d;
}
__device__ __forceinline__ float2 unpack2(ull v) {
    float2 r;
    asm("mov.b64 {%0, %1}, %2;" : "=f"(r.x), "=f"(r.y) : "l"(v));
    return r;
}

// ---------------------------------------------------------------------------
// Init: h from init_hx (broadcast over batch), reset barrier
// ---------------------------------------------------------------------------
__global__ void init_state(const float* __restrict__ init_hx) {
    int j = blockIdx.x * blockDim.x + threadIdx.x;
    if (j == 0) g_bar = 0;
    if (j < BB * OSZ) g_h[j] = init_hx[j & (OSZ - 1)];
}

// ---------------------------------------------------------------------------
// xproj[row, n] = b[n] + sum_k x[row, k] * W[k, n]
// FFMA2 packed along N: a float4 W load IS two {col, col+1} f32x2 operands
// (reinterpret, zero pack cost); x scalar splatted {x,x} with 1 ALU MOV.
// Block (32,8): thread = 4 rows x 4 cols (2 ull accumulators per row).
// ---------------------------------------------------------------------------
__global__ void xproj_kernel(const float* __restrict__ x,
                             const float* __restrict__ W,
                             const float* __restrict__ bias) {
    const int tx = threadIdx.x, ty = threadIdx.y;
    const int col0 = (blockIdx.x * 32 + tx) * 4;
    const int row0 = blockIdx.y * 32 + ty * 4;

    ull acc2[4][2];
    #pragma unroll
    for (int r = 0; r < 4; r++) { acc2[r][0] = 0ull; acc2[r][1] = 0ull; }

    const float* xp = x + (size_t)row0 * ISZ;

    #pragma unroll 2
    for (int k = 0; k < ISZ; k += 4) {
        float4 xv[4];
        #pragma unroll
        for (int r = 0; r < 4; r++)
            xv[r] = __ldg((const float4*)(xp + (size_t)r * ISZ + k));

        #pragma unroll
        for (int kk = 0; kk < 4; kk++) {
            ulonglong2 wp = *(const ulonglong2*)(W + (size_t)(k + kk) * N4 + col0);
            #pragma unroll
            for (int r = 0; r < 4; r++) {
                float xs = (kk == 0) ? xv[r].x : (kk == 1) ? xv[r].y
                         : (kk == 2) ? xv[r].z : xv[r].w;
                ull xd = splat2(xs);
                acc2[r][0] = ffma2(xd, wp.x, acc2[r][0]);
                acc2[r][1] = ffma2(xd, wp.y, acc2[r][1]);
            }
        }
    }

    float4 bv = *(const float4*)(bias + col0);
    #pragma unroll
    for (int r = 0; r < 4; r++) {
        float2 lo = unpack2(acc2[r][0]);
        float2 hi = unpack2(acc2[r][1]);
        float4 o;
        o.x = lo.x + bv.x;
        o.y = lo.y + bv.y;
        o.z = hi.x + bv.z;
        o.w = hi.y + bv.w;
        *(float4*)(g_xproj + (size_t)(row0 + r) * N4 + col0) = o;
    }
}

// ---------------------------------------------------------------------------
// Software grid barrier (all NBLK blocks co-resident: 1 block/SM by smem)
// ---------------------------------------------------------------------------
__device__ __forceinline__ void gsync(unsigned target) {
    __syncthreads();
    if (threadIdx.x == 0) {
        __threadfence();
        atomicAdd(&g_bar, 1u);
        while (*(volatile unsigned*)&g_bar < target) { }
        __threadfence();
    }
    __syncthreads();
}

// ---------------------------------------------------------------------------
// Persistent LSTM recurrence. (unchanged from round 5 -- proven)
// Block `blk` owns output cols {g*1024 + blk*8 + q}.
// Warp mapping: tx -> col, ty -> k-subrange [ty*32, ty*32+32) of each chunk,
// accumulating partials for ALL 32 batch rows (32 x f32x2 accumulators).
// ---------------------------------------------------------------------------
__global__ void __launch_bounds__(NTHR, 1)
lstm_persist(const float* __restrict__ W,
             const float* __restrict__ gamma,
             const float* __restrict__ beta,
             const float* __restrict__ init_cx,
             float* __restrict__ out) {
    extern __shared__ float smem[];
    float4* __restrict__ Wsf4 = (float4*)smem;               // [8192] float4
    float*  __restrict__ Hreg = smem + 32768;                // 64KB region
    float4* __restrict__ Hbuf = (float4*)Hreg;               // [2][2048] float4
    float*  __restrict__ Pred = Hreg;                        // overlay: [32][8][32]
    __shared__ float c_sm[BB * 8];

    const int tid = threadIdx.x;
    const int tx  = tid & 31, ty = tid >> 5;
    const int blk = blockIdx.x;
    const int g   = tx >> 3, q = tx & 7;
    const int gcol = g * OSZ + blk * 8 + q;
    const int b0  = ty * 4;

    // Preload W_h slice into float4 layout: smem[(k>>2)*128 + c*4 + (k&3)]
    for (int idx = tid; idx < ISZ * 32; idx += NTHR) {
        int k = idx >> 5, c = idx & 31;
        int col = (c >> 3) * OSZ + blk * 8 + (c & 7);
        smem[(k >> 2) * 128 + c * 4 + (k & 3)] = W[(size_t)(ISZ + k) * N4 + col];
    }
    if (tid < BB * 8)
        c_sm[tid] = init_cx[blk * 8 + (tid & 7)];

    const float gam = gamma[gcol];
    const float bet = beta[gcol];

    // Cooperative-load source indices (8 float4 per chunk per thread)
    int ld_r[8], ld_j[8];
    #pragma unroll
    for (int u = 0; u < 8; u++) {
        int i = u * NTHR + tid;
        ld_r[u] = i >> 6;
        ld_j[u] = i & 63;
    }
    __syncthreads();

    unsigned nsync = 0;

    // Prefetch xproj for t=0
    float px[4];
    #pragma unroll
    for (int r = 0; r < 4; r++)
        px[r] = __ldcg(&g_xproj[((size_t)(b0 + r) * SS + 0) * N4 + gcol]);

    for (int t = 0; t < SS; t++) {
        float cur[4];
        #pragma unroll
        for (int r = 0; r < 4; r++) cur[r] = px[r];
        if (t + 1 < SS) {
            #pragma unroll
            for (int r = 0; r < 4; r++)
                px[r] = __ldcg(&g_xproj[((size_t)(b0 + r) * SS + t + 1) * N4 + gcol]);
        }

        // ---- stage chunk 0 of h ----
        {
            float4 ld[8];
            #pragma unroll
            for (int u = 0; u < 8; u++)
                ld[u] = __ldcg((const float4*)(g_h + (size_t)ld_r[u] * OSZ + ld_j[u] * 4));
            #pragma unroll
            for (int u = 0; u < 8; u++)
                Hbuf[u * NTHR + tid] = ld[u];
        }
        __syncthreads();

        // ---- recurrent GEMM: warp ty covers k in [c*256+ty*32, +32) for
        //      all 32 rows; f32x2 accumulators, one per row ----
        ull acc2[32];
        #pragma unroll
        for (int r = 0; r < 32; r++) acc2[r] = 0ull;

        #pragma unroll 1
        for (int c = 0; c < NCH; c++) {
            float4 ldn[8];
            if (c < NCH - 1) {
                const int k0n = (c + 1) * CHUNK;
                #pragma unroll
                for (int u = 0; u < 8; u++)
                    ldn[u] = __ldcg((const float4*)(g_h + (size_t)ld_r[u] * OSZ + k0n + ld_j[u] * 4));
            }

            const float4* __restrict__ hb = Hbuf + (c & 1) * 2048;
            const ulonglong2* __restrict__ wp =
                (const ulonglong2*)Wsf4 + (size_t)(c * 64 + ty * 8) * 32 + tx;

            #pragma unroll 4
            for (int jj = 0; jj < 8; jj++) {
                ulonglong2 wv = wp[jj * 32];            // {w[k],w[k+1]},{w[k+2],w[k+3]}
                const ulonglong2* __restrict__ hj =
                    (const ulonglong2*)(hb + (ty * 8 + jj));
                #pragma unroll
                for (int r = 0; r < 32; r++) {
                    ulonglong2 hv = hj[r * 64];         // broadcast: h[r][k..k+3]
                    acc2[r] = ffma2(hv.x, wv.x, acc2[r]);
                    acc2[r] = ffma2(hv.y, wv.y, acc2[r]);
                }
            }

            if (c < NCH - 1) {
                float4* __restrict__ hn = Hbuf + ((c + 1) & 1) * 2048;
                #pragma unroll
                for (int u = 0; u < 8; u++)
                    hn[u * NTHR + tid] = ldn[u];
                __syncthreads();
            }
        }

        // ---- cross-warp k-reduction via SMEM overlay (buf0 region is dead:
        //      final chunk reads buf1 only) ----
        #pragma unroll
        for (int r = 0; r < 32; r++) {
            float2 a = unpack2(acc2[r]);
            Pred[(r * 8 + ty) * 32 + tx] = a.x + a.y;
        }
        __syncthreads();

        float acc[4];
        #pragma unroll
        for (int r = 0; r < 4; r++) {
            const int row = b0 + r;
            float sum = 0.f;
            #pragma unroll
            for (int w = 0; w < 8; w++)
                sum += Pred[(row * 8 + w) * 32 + tx];
            acc[r] = sum + cur[r];
        }

        // ---- LN partial sums over this block's 32 columns, per row ----
        float s[4], ss[4];
        #pragma unroll
        for (int r = 0; r < 4; r++) { s[r] = acc[r]; ss[r] = acc[r] * acc[r]; }
        #pragma unroll
        for (int o = 16; o > 0; o >>= 1) {
            #pragma unroll
            for (int r = 0; r < 4; r++) {
                s[r]  += __shfl_xor_sync(0xffffffffu, s[r],  o);
                ss[r] += __shfl_xor_sync(0xffffffffu, ss[r], o);
            }
        }
        if (tx == 0) {
            #pragma unroll
            for (int r = 0; r < 4; r++) {
                __stcg(&g_part[0][b0 + r][blk], s[r]);
                __stcg(&g_part[1][b0 + r][blk], ss[r]);
            }
        }

        gsync(++nsync * NBLK);

        // ---- aggregate stats (deterministic): warp ty handles rows b0..b0+3 ----
        float mean[4], rstd[4];
        #pragma unroll
        for (int r = 0; r < 4; r++) {
            int row = b0 + r;
            float4 sv = __ldcg((const float4*)&g_part[0][row][tx * 4]);
            float4 qv = __ldcg((const float4*)&g_part[1][row][tx * 4]);
            float sl = (sv.x + sv.y) + (sv.z + sv.w);
            float ql = (qv.x + qv.y) + (qv.z + qv.w);
            #pragma unroll
            for (int o = 16; o > 0; o >>= 1) {
                sl += __shfl_xor_sync(0xffffffffu, sl, o);
                ql += __shfl_xor_sync(0xffffffffu, ql, o);
            }
            float m = sl * (1.0f / N4);
            mean[r] = m;
            rstd[r] = rsqrtf(ql * (1.0f / N4) - m * m + EPSF);
        }

        // ---- LN + gates. Gates of index i sit in lanes q, q+8, q+16, q+24 ----
        #pragma unroll
        for (int r = 0; r < 4; r++) {
            float v = (acc[r] - mean[r]) * rstd[r] * gam + bet;
            float a0 = __shfl_sync(0xffffffffu, v, q);        // ig
            float a1 = __shfl_sync(0xffffffffu, v, q + 8);    // fg
            float a2 = __shfl_sync(0xffffffffu, v, q + 16);   // hidden
            float a3 = __shfl_sync(0xffffffffu, v, q + 24);   // og
            if (g == 0) {
                int b = b0 + r;
                int i = blk * 8 + q;
                float si = 1.0f / (1.0f + expf(-a0));
                float sf = 1.0f / (1.0f + expf(-a1));
                float so = 1.0f / (1.0f + expf(-a3));
                float co = c_sm[b * 8 + q];
                float cn = sf * co + si * tanhf(a2);
                float h  = so * cn;
                c_sm[b * 8 + q] = cn;
                __stcg(&g_h[(size_t)b * OSZ + i], h);
                out[((size_t)b * SS + t) * OSZ + i] = h;
            }
        }

        gsync(++nsync * NBLK);
    }
}

// ---------------------------------------------------------------------------
// Inputs (metadata order): x, W, b, gamma, beta, init_hx, init_cx
// ---------------------------------------------------------------------------
extern "C" void kernel_launch(void* const* d_in, const int* in_sizes, int n_in,
                              void* d_out, int out_size) {
    const float* x       = (const float*)d_in[0];
    const float* W       = (const float*)d_in[1];
    const float* bias    = (const float*)d_in[2];
    const float* gamma   = (const float*)d_in[3];
    const float* beta    = (const float*)d_in[4];
    const float* init_hx = (const float*)d_in[5];
    const float* init_cx = (const float*)d_in[6];
    float* out = (float*)d_out;

    init_state<<<(BB * OSZ + 255) / 256, 256>>>(init_hx);

    dim3 blk(32, 8);
    xproj_kernel<<<dim3(32, 256), blk>>>(x, W, bias);

    cudaFuncSetAttribute(lstm_persist,
                         cudaFuncAttributeMaxDynamicSharedMemorySize, 196608);
    lstm_persist<<<NBLK, NTHR, 196608>>>(W, gamma, beta, init_cx, out);
}